// round 1
// baseline (speedup 1.0000x reference)
#include <cuda_runtime.h>
#include <math.h>

#define NPIX 65536
#define BTOT 4

// ---------------- scratch (static device globals; no allocation at runtime) ----
__device__ float g_h [16777216];                 // LN1 output        (B,64,N)
__device__ float g_g [16777216];                 // dwconv output     (B,64,N)
__device__ float g_q [16777216];                 // q                 (B,64,N)
__device__ float g_k [16777216];                 // k
__device__ float g_v [16777216];                 // v
__device__ float g_xn[16777216];                 // x + attn_proj     (B,64,N)
__device__ float g_m [67108864];                 // mlp_in output     (B,256,N)
__device__ float g_gt[16777216];                 // gated+BN          (B,64,N)
__device__ float g_sq[256];                      // sum q^2 per (b,chan)
__device__ float g_sk[256];
__device__ float g_sv[256];
__device__ float g_gram[2048];                   // (b,h,d,e)
__device__ float g_W[2048];                      // softmax weights with 1/||v|| folded in

// ---------------- K0: zero accumulators (graph replays reuse globals) ----------
__global__ void k_zero() {
    int t = blockIdx.x * 256 + threadIdx.x;
    if (t < 256) { g_sq[t] = 0.f; g_sk[t] = 0.f; g_sv[t] = 0.f; }
    if (t < 2048) g_gram[t] = 0.f;
}

// ---------------- K1: LayerNorm over C=64 per pixel ----------------------------
__global__ void __launch_bounds__(256) k_ln1(const float* __restrict__ x,
                                             const float* __restrict__ w,
                                             const float* __restrict__ bia) {
    int p = blockIdx.x * 256 + threadIdx.x;       // 0..B*N-1
    int bb = p >> 16, pix = p & 65535;
    size_t base = ((size_t)bb << 22) + pix;
    float v[64]; float mu = 0.f;
    #pragma unroll
    for (int c = 0; c < 64; c++) { v[c] = x[base + ((size_t)c << 16)]; mu += v[c]; }
    mu *= 0.015625f;
    float var = 0.f;
    #pragma unroll
    for (int c = 0; c < 64; c++) { float d = v[c] - mu; var += d * d; }
    var *= 0.015625f;
    float rs = rsqrtf(var + 1e-5f);
    #pragma unroll
    for (int c = 0; c < 64; c++)
        g_h[base + ((size_t)c << 16)] = (v[c] - mu) * rs * w[c] + bia[c];
}

// ---------------- K2: 3x3 depthwise conv, zero pad ('SAME') --------------------
__global__ void __launch_bounds__(256) k_dw(const float* __restrict__ w) {
    int idx = blockIdx.x * 256 + threadIdx.x;     // over B*64*N = 16.7M
    int pix = idx & 65535; int bc = idx >> 16; int c = bc & 63;
    int r = pix >> 8, cl = pix & 255;
    const float* pl = g_h + ((size_t)bc << 16);
    const float* wt = w + c * 9;
    float acc = 0.f;
    #pragma unroll
    for (int dy = 0; dy < 3; dy++) {
        int rr = r + dy - 1;
        if ((unsigned)rr > 255u) continue;
        #pragma unroll
        for (int dx = 0; dx < 3; dx++) {
            int cc = cl + dx - 1;
            if ((unsigned)cc > 255u) continue;
            acc += wt[dy * 3 + dx] * pl[(rr << 8) + cc];
        }
    }
    g_g[idx] = acc;
}

// ---------------- K3: q/k/v 1x1 convs (3x 64x64 GEMM per pixel) -----------------
__global__ void __launch_bounds__(256) k_qkv(const float* __restrict__ qw,
                                             const float* __restrict__ kw,
                                             const float* __restrict__ vw) {
    __shared__ float s[12288];                    // 48KB: q_w | k_w | v_w
    int tid = threadIdx.x;
    for (int i = tid; i < 4096; i += 256) {
        s[i] = qw[i]; s[4096 + i] = kw[i]; s[8192 + i] = vw[i];
    }
    __syncthreads();
    int p = blockIdx.x * 256 + tid; int bb = p >> 16, pix = p & 65535;
    size_t base = ((size_t)bb << 22) + pix;
    float in[64];
    #pragma unroll
    for (int c = 0; c < 64; c++) in[c] = g_g[base + ((size_t)c << 16)];
    #pragma unroll 2
    for (int o = 0; o < 64; o++) {
        const float4* rq = (const float4*)(s + (o << 6));
        const float4* rk = (const float4*)(s + 4096 + (o << 6));
        const float4* rv = (const float4*)(s + 8192 + (o << 6));
        float aq = 0.f, ak = 0.f, av = 0.f;
        #pragma unroll
        for (int c4 = 0; c4 < 16; c4++) {
            float4 a = rq[c4], b2 = rk[c4], d = rv[c4];
            float i0 = in[4*c4], i1 = in[4*c4+1], i2 = in[4*c4+2], i3 = in[4*c4+3];
            aq += a.x*i0 + a.y*i1 + a.z*i2 + a.w*i3;
            ak += b2.x*i0 + b2.y*i1 + b2.z*i2 + b2.w*i3;
            av += d.x*i0 + d.y*i1 + d.z*i2 + d.w*i3;
        }
        size_t oi = base + ((size_t)o << 16);
        g_q[oi] = aq; g_k[oi] = ak; g_v[oi] = av;
    }
}

// ---------------- K4: per-(b,head) Gram + sum-of-squares reduction --------------
__global__ void __launch_bounds__(256) k_stats() {
    int tid = threadIdx.x;
    int chunk = blockIdx.x, hh = blockIdx.y, bb = blockIdx.z;
    float aq[8] = {0}, ak[8] = {0}, av[8] = {0}, G[64] = {0};
    size_t hbase = ((size_t)bb << 22) + ((size_t)(hh << 3) << 16);
    for (int it = 0; it < 4; it++) {
        int p = chunk * 1024 + it * 256 + tid;
        float qv[8], kv[8], vv[8];
        #pragma unroll
        for (int j = 0; j < 8; j++) {
            size_t idx = hbase + ((size_t)j << 16) + p;
            qv[j] = g_q[idx]; kv[j] = g_k[idx]; vv[j] = g_v[idx];
        }
        #pragma unroll
        for (int j = 0; j < 8; j++) {
            aq[j] += qv[j]*qv[j]; ak[j] += kv[j]*kv[j]; av[j] += vv[j]*vv[j];
        }
        #pragma unroll
        for (int d = 0; d < 8; d++)
            #pragma unroll
            for (int e = 0; e < 8; e++) G[d*8+e] += qv[d]*kv[e];
    }
    // warp butterfly reduce
    #pragma unroll
    for (int off = 16; off; off >>= 1) {
        #pragma unroll
        for (int j = 0; j < 8; j++) {
            aq[j] += __shfl_xor_sync(~0u, aq[j], off);
            ak[j] += __shfl_xor_sync(~0u, ak[j], off);
            av[j] += __shfl_xor_sync(~0u, av[j], off);
        }
        #pragma unroll
        for (int j = 0; j < 64; j++) G[j] += __shfl_xor_sync(~0u, G[j], off);
    }
    __shared__ float red[88];
    if (tid < 88) red[tid] = 0.f;
    __syncthreads();
    if ((tid & 31) == 0) {
        #pragma unroll
        for (int j = 0; j < 8; j++) {
            atomicAdd(&red[j], aq[j]); atomicAdd(&red[8+j], ak[j]); atomicAdd(&red[16+j], av[j]);
        }
        #pragma unroll
        for (int j = 0; j < 64; j++) atomicAdd(&red[24+j], G[j]);
    }
    __syncthreads();
    if (tid < 8)        atomicAdd(&g_sq[bb*64 + hh*8 + tid],        red[tid]);
    else if (tid < 16)  atomicAdd(&g_sk[bb*64 + hh*8 + tid - 8],    red[tid]);
    else if (tid < 24)  atomicAdd(&g_sv[bb*64 + hh*8 + tid - 16],   red[tid]);
    else if (tid < 88)  atomicAdd(&g_gram[(bb*8 + hh)*64 + tid-24], red[tid]);
}

// ---------------- K5: softmax weights with v-norm folded in ---------------------
__global__ void k_attw() {
    int t = threadIdx.x;            // 256 threads == (b,h,d)
    int d = t & 7; int bh = t >> 3; int bb = bh >> 3; int hh = bh & 7;
    float nq = fmaxf(sqrtf(g_sq[bb*64 + hh*8 + d]), 1e-12f);
    const float scale = 0.35355339059327373f;     // 8^-0.5
    float row[8]; float mx = -1e30f;
    #pragma unroll
    for (int e = 0; e < 8; e++) {
        float ne = fmaxf(sqrtf(g_sk[bb*64 + hh*8 + e]), 1e-12f);
        row[e] = g_gram[bh*64 + d*8 + e] * scale / (nq * ne);
        mx = fmaxf(mx, row[e]);
    }
    float sum = 0.f;
    #pragma unroll
    for (int e = 0; e < 8; e++) { row[e] = expf(row[e] - mx); sum += row[e]; }
    float inv = 1.f / sum;
    #pragma unroll
    for (int e = 0; e < 8; e++) {
        float nv = fmaxf(sqrtf(g_sv[bb*64 + hh*8 + e]), 1e-12f);
        g_W[bh*64 + d*8 + e] = row[e] * inv / nv;
    }
}

// ---------------- K6: attn-out + proj + residual + LN2 + mlp_in -----------------
__global__ void __launch_bounds__(256) k_fuse(const float* __restrict__ x,
                                              const float* __restrict__ projw,
                                              const float* __restrict__ ln2w,
                                              const float* __restrict__ ln2b,
                                              const float* __restrict__ mlpw) {
    extern __shared__ float s[];
    float* sW  = s;            // 512
    float* sp  = s + 512;      // 4096 (proj_w)
    float* smw = s + 4608;     // 16384 (mlp_in_w)
    float* slw = s + 20992;    // 64
    float* slb = s + 21056;    // 64
    int tid = threadIdx.x; int bb = blockIdx.y;
    for (int i = tid; i < 512;   i += 256) sW[i]  = g_W[bb*512 + i];
    for (int i = tid; i < 4096;  i += 256) sp[i]  = projw[i];
    for (int i = tid; i < 16384; i += 256) smw[i] = mlpw[i];
    if (tid < 64) { slw[tid] = ln2w[tid]; slb[tid] = ln2b[tid]; }
    __syncthreads();
    int pix = blockIdx.x * 256 + tid;
    size_t base = ((size_t)bb << 22) + pix;
    float vec[64];
    #pragma unroll
    for (int c = 0; c < 64; c++) vec[c] = g_v[base + ((size_t)c << 16)];
    // attention output: per head 8x8 mix (normalization already folded into W)
    #pragma unroll
    for (int hh = 0; hh < 8; hh++) {
        float tmp[8];
        #pragma unroll
        for (int d = 0; d < 8; d++) {
            float a = 0.f;
            #pragma unroll
            for (int e = 0; e < 8; e++) a += sW[(hh<<6)+(d<<3)+e] * vec[(hh<<3)+e];
            tmp[d] = a;
        }
        #pragma unroll
        for (int d = 0; d < 8; d++) vec[(hh<<3)+d] = tmp[d];
    }
    // proj (must be fully unrolled: y[] register array)
    float y[64];
    #pragma unroll
    for (int oc = 0; oc < 64; oc++) {
        const float4* wr = (const float4*)(sp + (oc << 6));
        float a = 0.f;
        #pragma unroll
        for (int c4 = 0; c4 < 16; c4++) {
            float4 w4 = wr[c4];
            a += w4.x*vec[4*c4] + w4.y*vec[4*c4+1] + w4.z*vec[4*c4+2] + w4.w*vec[4*c4+3];
        }
        y[oc] = a;
    }
    // residual, store xn, LN2
    float mu = 0.f;
    #pragma unroll
    for (int c = 0; c < 64; c++) { y[c] += x[base + ((size_t)c << 16)]; mu += y[c]; }
    mu *= 0.015625f;
    float var = 0.f;
    #pragma unroll
    for (int c = 0; c < 64; c++) {
        float d = y[c] - mu; var += d * d;
        g_xn[base + ((size_t)c << 16)] = y[c];
    }
    var *= 0.015625f;
    float rs = rsqrtf(var + 1e-5f);
    #pragma unroll
    for (int c = 0; c < 64; c++) vec[c] = (y[c] - mu) * rs * slw[c] + slb[c];
    // mlp_in: 256 outputs
    size_t mbase = ((size_t)bb << 24) + pix;
    #pragma unroll 2
    for (int o = 0; o < 256; o++) {
        const float4* wr = (const float4*)(smw + (o << 6));
        float a = 0.f;
        #pragma unroll
        for (int c4 = 0; c4 < 16; c4++) {
            float4 w4 = wr[c4];
            a += w4.x*vec[4*c4] + w4.y*vec[4*c4+1] + w4.z*vec[4*c4+2] + w4.w*vec[4*c4+3];
        }
        g_m[mbase + ((size_t)o << 16)] = a;
    }
}

// ---------------- K7a: grouped 3x3 (reflect pad) + SiLU gate + BN ---------------
__global__ void __launch_bounds__(256) k_mlpdw(const float* __restrict__ dww,
                                               const float* __restrict__ bng,
                                               const float* __restrict__ bnb,
                                               const float* __restrict__ bnm,
                                               const float* __restrict__ bnv) {
    __shared__ float sw[4608];
    __shared__ float ssc[64], ssh[64];
    int tid = threadIdx.x;
    for (int i = tid; i < 4608; i += 256) sw[i] = dww[i];
    if (tid < 64) {
        float sc = bng[tid] * rsqrtf(bnv[tid] + 1e-5f);
        ssc[tid] = sc; ssh[tid] = bnb[tid] - bnm[tid] * sc;
    }
    __syncthreads();
    int t = blockIdx.x * 256 + tid;               // 65536 threads, 4 px each
    int p4 = t << 2;
    int bb = p4 >> 16, pix = p4 & 65535;
    int r = pix >> 8, c0 = pix & 255;
    int rm = r ? r - 1 : 1;
    int rp = (r == 255) ? 254 : r + 1;
    int ro0 = rm << 8, ro1 = r << 8, ro2 = rp << 8;
    int cols[6];
    #pragma unroll
    for (int k = 0; k < 6; k++) {
        int cx = c0 + k - 1;
        cols[k] = cx < 0 ? -cx : (cx > 255 ? 510 - cx : cx);
    }
    const float* mb = g_m + ((size_t)bb << 24);
    size_t obase = ((size_t)bb << 22) + pix;
    for (int cc = 0; cc < 32; cc++) {
        float A[4]={0,0,0,0}, Bx[4]={0,0,0,0}, Cx[4]={0,0,0,0}, Dx[4]={0,0,0,0};
        const float* w1a = sw + (2*cc)    * 36;
        const float* w1b = sw + (2*cc+1)  * 36;
        const float* w2a = sw + (64+2*cc) * 36;
        const float* w2b = sw + (65+2*cc) * 36;
        #pragma unroll
        for (int i = 0; i < 4; i++) {
            const float* p1 = mb + ((size_t)(4*cc + i)       << 16);
            const float* p2 = mb + ((size_t)(128 + 4*cc + i) << 16);
            float v1[18], v2[18];
            #pragma unroll
            for (int k = 0; k < 6; k++) {
                v1[k]    = p1[ro0 + cols[k]]; v1[6+k]  = p1[ro1 + cols[k]]; v1[12+k] = p1[ro2 + cols[k]];
                v2[k]    = p2[ro0 + cols[k]]; v2[6+k]  = p2[ro1 + cols[k]]; v2[12+k] = p2[ro2 + cols[k]];
            }
            #pragma unroll
            for (int ky = 0; ky < 3; ky++)
                #pragma unroll
                for (int kx = 0; kx < 3; kx++) {
                    float wa = w1a[i*9+ky*3+kx], wb = w1b[i*9+ky*3+kx];
                    float wc = w2a[i*9+ky*3+kx], wd = w2b[i*9+ky*3+kx];
                    #pragma unroll
                    for (int j = 0; j < 4; j++) {
                        float u1 = v1[ky*6 + j + kx], u2 = v2[ky*6 + j + kx];
                        A[j]  += wa * u1; Bx[j] += wb * u1;
                        Cx[j] += wc * u2; Dx[j] += wd * u2;
                    }
                }
        }
        int c1 = 2*cc, c2 = 2*cc + 1;
        float r1[4], r2[4];
        #pragma unroll
        for (int j = 0; j < 4; j++) {
            float s1 = A[j]  / (1.f + expf(-A[j]))  * Cx[j];
            float s2 = Bx[j] / (1.f + expf(-Bx[j])) * Dx[j];
            r1[j] = s1 * ssc[c1] + ssh[c1];
            r2[j] = s2 * ssc[c2] + ssh[c2];
        }
        *(float4*)(&g_gt[obase + ((size_t)c1 << 16)]) = make_float4(r1[0], r1[1], r1[2], r1[3]);
        *(float4*)(&g_gt[obase + ((size_t)c2 << 16)]) = make_float4(r2[0], r2[1], r2[2], r2[3]);
    }
}

// ---------------- K7b: out_w 1x1 + final residual -------------------------------
__global__ void __launch_bounds__(256) k_out(const float* __restrict__ ow,
                                             float* __restrict__ out) {
    __shared__ float s[4096];
    int tid = threadIdx.x;
    for (int i = tid; i < 4096; i += 256) s[i] = ow[i];
    __syncthreads();
    int p = blockIdx.x * 256 + tid; int bb = p >> 16, pix = p & 65535;
    size_t base = ((size_t)bb << 22) + pix;
    float in[64];
    #pragma unroll
    for (int c = 0; c < 64; c++) in[c] = g_gt[base + ((size_t)c << 16)];
    #pragma unroll 2
    for (int oc = 0; oc < 64; oc++) {
        const float4* wr = (const float4*)(s + (oc << 6));
        float a = 0.f;
        #pragma unroll
        for (int c4 = 0; c4 < 16; c4++) {
            float4 w4 = wr[c4];
            a += w4.x*in[4*c4] + w4.y*in[4*c4+1] + w4.z*in[4*c4+2] + w4.w*in[4*c4+3];
        }
        size_t oi = base + ((size_t)oc << 16);
        out[oi] = g_xn[oi] + a;
    }
}

// ---------------- launch ---------------------------------------------------------
extern "C" void kernel_launch(void* const* d_in, const int* in_sizes, int n_in,
                              void* d_out, int out_size) {
    const float* x     = (const float*)d_in[0];
    const float* ln1w  = (const float*)d_in[1];
    const float* ln1b  = (const float*)d_in[2];
    const float* ln2w  = (const float*)d_in[3];
    const float* ln2b  = (const float*)d_in[4];
    const float* dww   = (const float*)d_in[5];
    const float* qw    = (const float*)d_in[6];
    const float* kw    = (const float*)d_in[7];
    const float* vw    = (const float*)d_in[8];
    const float* projw = (const float*)d_in[9];
    const float* mlpw  = (const float*)d_in[10];
    const float* mdww  = (const float*)d_in[11];
    const float* bng   = (const float*)d_in[12];
    const float* bnb   = (const float*)d_in[13];
    const float* bnm   = (const float*)d_in[14];
    const float* bnv   = (const float*)d_in[15];
    const float* ow    = (const float*)d_in[16];
    float* out = (float*)d_out;

    cudaFuncSetAttribute(k_fuse, cudaFuncAttributeMaxDynamicSharedMemorySize, 21120 * 4);

    k_zero<<<8, 256>>>();
    k_ln1<<<1024, 256>>>(x, ln1w, ln1b);
    k_dw<<<65536, 256>>>(dww);
    k_qkv<<<1024, 256>>>(qw, kw, vw);
    dim3 gs(64, 8, 4);
    k_stats<<<gs, 256>>>();
    k_attw<<<1, 256>>>();
    dim3 gf(256, 4);
    k_fuse<<<gf, 256, 21120 * 4>>>(x, projw, ln2w, ln2b, mlpw);
    k_mlpdw<<<256, 256>>>(mdww, bng, bnb, bnm, bnv);
    k_out<<<1024, 256>>>(ow, out);
}

// round 2
// speedup vs baseline: 1.1012x; 1.1012x over previous
#include <cuda_runtime.h>
#include <math.h>

// ---------------- scratch (static device globals) ------------------------------
__device__ float g_h [16777216];                 // LN1 output        (B,64,N)
__device__ float g_g [16777216];                 // dwconv output     (B,64,N)
__device__ float g_q [16777216];                 // q
__device__ float g_k [16777216];                 // k
__device__ float g_v [16777216];                 // v
__device__ float g_xn[16777216];                 // x + attn_proj
__device__ float g_m [67108864];                 // mlp_in output     (B,256,N)
__device__ float g_gt[16777216];                 // gated+BN
__device__ float g_sq[256];
__device__ float g_sk[256];
__device__ float g_sv[256];
__device__ float g_gram[2048];
__device__ float g_W[2048];                      // softmax weights, 1/||v|| folded
__device__ float g_M[16384];                     // per-batch combined proj*attn (4 x 64 x 64)

// ---------------- f32x2 helpers -------------------------------------------------
__device__ __forceinline__ unsigned long long pk2(float a, float b) {
    unsigned long long r;
    asm("mov.b64 %0, {%1, %2};" : "=l"(r) : "f"(a), "f"(b));
    return r;
}
__device__ __forceinline__ void fma2(unsigned long long& acc, unsigned long long w,
                                     unsigned long long v) {
    asm("fma.rn.f32x2 %0, %1, %2, %0;" : "+l"(acc) : "l"(w), "l"(v));
}
__device__ __forceinline__ float hadd2(unsigned long long a) {
    float lo, hi;
    asm("mov.b64 {%0, %1}, %2;" : "=f"(lo), "=f"(hi) : "l"(a));
    return lo + hi;
}

// ---------------- K0: zero accumulators -----------------------------------------
__global__ void k_zero() {
    int t = blockIdx.x * 256 + threadIdx.x;
    if (t < 256) { g_sq[t] = 0.f; g_sk[t] = 0.f; g_sv[t] = 0.f; }
    if (t < 2048) g_gram[t] = 0.f;
}

// ---------------- K1: LayerNorm over C=64 per pixel -----------------------------
__global__ void __launch_bounds__(256) k_ln1(const float* __restrict__ x,
                                             const float* __restrict__ w,
                                             const float* __restrict__ bia) {
    int p = blockIdx.x * 256 + threadIdx.x;
    int bb = p >> 16, pix = p & 65535;
    size_t base = ((size_t)bb << 22) + pix;
    float v[64]; float mu = 0.f;
    #pragma unroll
    for (int c = 0; c < 64; c++) { v[c] = x[base + ((size_t)c << 16)]; mu += v[c]; }
    mu *= 0.015625f;
    float var = 0.f;
    #pragma unroll
    for (int c = 0; c < 64; c++) { float d = v[c] - mu; var += d * d; }
    var *= 0.015625f;
    float rs = rsqrtf(var + 1e-5f);
    #pragma unroll
    for (int c = 0; c < 64; c++)
        g_h[base + ((size_t)c << 16)] = (v[c] - mu) * rs * w[c] + bia[c];
}

// ---------------- K2: 3x3 depthwise conv, zero pad ------------------------------
__global__ void __launch_bounds__(256) k_dw(const float* __restrict__ w) {
    int idx = blockIdx.x * 256 + threadIdx.x;
    int pix = idx & 65535; int bc = idx >> 16; int c = bc & 63;
    int r = pix >> 8, cl = pix & 255;
    const float* pl = g_h + ((size_t)bc << 16);
    const float* wt = w + c * 9;
    float acc = 0.f;
    #pragma unroll
    for (int dy = 0; dy < 3; dy++) {
        int rr = r + dy - 1;
        if ((unsigned)rr > 255u) continue;
        #pragma unroll
        for (int dx = 0; dx < 3; dx++) {
            int cc = cl + dx - 1;
            if ((unsigned)cc > 255u) continue;
            acc += wt[dy * 3 + dx] * pl[(rr << 8) + cc];
        }
    }
    g_g[idx] = acc;
}

// ---------------- K3: q/k/v 1x1 convs, f32x2 channel-pair packing ---------------
__global__ void __launch_bounds__(256) k_qkv(const float* __restrict__ qw,
                                             const float* __restrict__ kw,
                                             const float* __restrict__ vw) {
    __shared__ __align__(16) float s[12288];
    int tid = threadIdx.x;
    for (int i = tid; i < 4096; i += 256) {
        s[i] = qw[i]; s[4096 + i] = kw[i]; s[8192 + i] = vw[i];
    }
    __syncthreads();
    int p = blockIdx.x * 256 + tid; int bb = p >> 16, pix = p & 65535;
    size_t base = ((size_t)bb << 22) + pix;
    unsigned long long inp[32];
    #pragma unroll
    for (int c = 0; c < 32; c++) {
        float a = g_g[base + ((size_t)(2 * c) << 16)];
        float b = g_g[base + ((size_t)(2 * c + 1) << 16)];
        inp[c] = pk2(a, b);
    }
    #pragma unroll 2
    for (int o = 0; o < 64; o++) {
        const ulonglong2* rq = (const ulonglong2*)(s + (o << 6));
        const ulonglong2* rk = (const ulonglong2*)(s + 4096 + (o << 6));
        const ulonglong2* rv = (const ulonglong2*)(s + 8192 + (o << 6));
        unsigned long long aq = 0ull, ak = 0ull, av = 0ull;
        #pragma unroll
        for (int c4 = 0; c4 < 16; c4++) {
            ulonglong2 wq = rq[c4], wk = rk[c4], wv = rv[c4];
            fma2(aq, wq.x, inp[2 * c4]); fma2(aq, wq.y, inp[2 * c4 + 1]);
            fma2(ak, wk.x, inp[2 * c4]); fma2(ak, wk.y, inp[2 * c4 + 1]);
            fma2(av, wv.x, inp[2 * c4]); fma2(av, wv.y, inp[2 * c4 + 1]);
        }
        size_t oi = base + ((size_t)o << 16);
        g_q[oi] = hadd2(aq); g_k[oi] = hadd2(ak); g_v[oi] = hadd2(av);
    }
}

// ---------------- K4: Gram + sum-of-squares reduction (8 chunks, 32px/thread) ---
__global__ void __launch_bounds__(256) k_stats() {
    int tid = threadIdx.x;
    int chunk = blockIdx.x, hh = blockIdx.y, bb = blockIdx.z;
    float aq[8] = {0}, ak[8] = {0}, av[8] = {0}, G[64] = {0};
    size_t hbase = ((size_t)bb << 22) + ((size_t)(hh << 3) << 16);
    for (int it = 0; it < 32; it++) {
        int p = chunk * 8192 + it * 256 + tid;
        float qv[8], kv[8], vv[8];
        #pragma unroll
        for (int j = 0; j < 8; j++) {
            size_t idx = hbase + ((size_t)j << 16) + p;
            qv[j] = g_q[idx]; kv[j] = g_k[idx]; vv[j] = g_v[idx];
        }
        #pragma unroll
        for (int j = 0; j < 8; j++) {
            aq[j] += qv[j]*qv[j]; ak[j] += kv[j]*kv[j]; av[j] += vv[j]*vv[j];
        }
        #pragma unroll
        for (int d = 0; d < 8; d++)
            #pragma unroll
            for (int e = 0; e < 8; e++) G[d*8+e] += qv[d]*kv[e];
    }
    #pragma unroll
    for (int off = 16; off; off >>= 1) {
        #pragma unroll
        for (int j = 0; j < 8; j++) {
            aq[j] += __shfl_xor_sync(~0u, aq[j], off);
            ak[j] += __shfl_xor_sync(~0u, ak[j], off);
            av[j] += __shfl_xor_sync(~0u, av[j], off);
        }
        #pragma unroll
        for (int j = 0; j < 64; j++) G[j] += __shfl_xor_sync(~0u, G[j], off);
    }
    __shared__ float red[88];
    if (tid < 88) red[tid] = 0.f;
    __syncthreads();
    if ((tid & 31) == 0) {
        #pragma unroll
        for (int j = 0; j < 8; j++) {
            atomicAdd(&red[j], aq[j]); atomicAdd(&red[8+j], ak[j]); atomicAdd(&red[16+j], av[j]);
        }
        #pragma unroll
        for (int j = 0; j < 64; j++) atomicAdd(&red[24+j], G[j]);
    }
    __syncthreads();
    if (tid < 8)        atomicAdd(&g_sq[bb*64 + hh*8 + tid],        red[tid]);
    else if (tid < 16)  atomicAdd(&g_sk[bb*64 + hh*8 + tid - 8],    red[tid]);
    else if (tid < 24)  atomicAdd(&g_sv[bb*64 + hh*8 + tid - 16],   red[tid]);
    else if (tid < 88)  atomicAdd(&g_gram[(bb*8 + hh)*64 + tid-24], red[tid]);
}

// ---------------- K5: softmax weights with v-norm folded ------------------------
__global__ void k_attw() {
    int t = threadIdx.x;
    int d = t & 7; int bh = t >> 3; int bb = bh >> 3; int hh = bh & 7;
    float nq = fmaxf(sqrtf(g_sq[bb*64 + hh*8 + d]), 1e-12f);
    const float scale = 0.35355339059327373f;
    float row[8]; float mx = -1e30f;
    #pragma unroll
    for (int e = 0; e < 8; e++) {
        float ne = fmaxf(sqrtf(g_sk[bb*64 + hh*8 + e]), 1e-12f);
        row[e] = g_gram[bh*64 + d*8 + e] * scale / (nq * ne);
        mx = fmaxf(mx, row[e]);
    }
    float sum = 0.f;
    #pragma unroll
    for (int e = 0; e < 8; e++) { row[e] = expf(row[e] - mx); sum += row[e]; }
    float inv = 1.f / sum;
    #pragma unroll
    for (int e = 0; e < 8; e++) {
        float nv = fmaxf(sqrtf(g_sv[bb*64 + hh*8 + e]), 1e-12f);
        g_W[bh*64 + d*8 + e] = row[e] * inv / nv;
    }
}

// ---------------- K5b: combined M_b = proj * blockdiag(W) -----------------------
__global__ void k_mix(const float* __restrict__ projw) {
    int bb = blockIdx.x; int oc = threadIdx.x;      // 64 threads
    for (int c = 0; c < 64; c++) {
        int h = c >> 3, e = c & 7;
        float a = 0.f;
        #pragma unroll
        for (int d = 0; d < 8; d++)
            a += projw[oc*64 + (h<<3) + d] * g_W[((bb<<3) + h)*64 + (d<<3) + e];
        g_M[bb*4096 + oc*64 + c] = a;
    }
}

// ---------------- K6: (attn+proj) + residual + LN2 + mlp_in, f32x2 --------------
__global__ void __launch_bounds__(256) k_fuse(const float* __restrict__ x,
                                              const float* __restrict__ ln2w,
                                              const float* __restrict__ ln2b,
                                              const float* __restrict__ mlpw) {
    extern __shared__ __align__(16) float s[];
    float* sM  = s;            // 4096  (combined attn+proj)
    float* smw = s + 4096;     // 16384 (mlp_in_w)
    float* slw = s + 20480;    // 64
    float* slb = s + 20544;    // 64
    int tid = threadIdx.x; int bb = blockIdx.y;
    for (int i = tid; i < 4096;  i += 256) sM[i]  = g_M[bb*4096 + i];
    for (int i = tid; i < 16384; i += 256) smw[i] = mlpw[i];
    if (tid < 64) { slw[tid] = ln2w[tid]; slb[tid] = ln2b[tid]; }
    __syncthreads();
    int pix = blockIdx.x * 256 + tid;
    size_t base = ((size_t)bb << 22) + pix;
    unsigned long long vp[32];
    #pragma unroll
    for (int c = 0; c < 32; c++) {
        float a = g_v[base + ((size_t)(2*c)   << 16)];
        float b = g_v[base + ((size_t)(2*c+1) << 16)];
        vp[c] = pk2(a, b);
    }
    // y = M * v + x   (attn+proj combined), store xn, LN2 stats
    float y[64]; float mu = 0.f;
    #pragma unroll
    for (int oc = 0; oc < 64; oc++) {
        const ulonglong2* row = (const ulonglong2*)(sM + (oc << 6));
        unsigned long long acc = 0ull;
        #pragma unroll
        for (int c4 = 0; c4 < 16; c4++) {
            ulonglong2 w2 = row[c4];
            fma2(acc, w2.x, vp[2*c4]); fma2(acc, w2.y, vp[2*c4+1]);
        }
        y[oc] = hadd2(acc) + x[base + ((size_t)oc << 16)];
        mu += y[oc];
    }
    mu *= 0.015625f;
    float var = 0.f;
    #pragma unroll
    for (int c = 0; c < 64; c++) {
        float d = y[c] - mu; var += d * d;
        g_xn[base + ((size_t)c << 16)] = y[c];
    }
    var *= 0.015625f;
    float rs = rsqrtf(var + 1e-5f);
    #pragma unroll
    for (int c = 0; c < 32; c++) {
        float a = (y[2*c]   - mu) * rs * slw[2*c]   + slb[2*c];
        float b = (y[2*c+1] - mu) * rs * slw[2*c+1] + slb[2*c+1];
        vp[c] = pk2(a, b);
    }
    // mlp_in: 256 outputs
    size_t mbase = ((size_t)bb << 24) + pix;
    #pragma unroll 4
    for (int o = 0; o < 256; o++) {
        const ulonglong2* row = (const ulonglong2*)(smw + (o << 6));
        unsigned long long acc = 0ull;
        #pragma unroll
        for (int c4 = 0; c4 < 16; c4++) {
            ulonglong2 w2 = row[c4];
            fma2(acc, w2.x, vp[2*c4]); fma2(acc, w2.y, vp[2*c4+1]);
        }
        g_m[mbase + ((size_t)o << 16)] = hadd2(acc);
    }
}

// ---------------- K7a: grouped 3x3 (reflect pad) + SiLU gate + BN ---------------
__global__ void __launch_bounds__(256) k_mlpdw(const float* __restrict__ dww,
                                               const float* __restrict__ bng,
                                               const float* __restrict__ bnb,
                                               const float* __restrict__ bnm,
                                               const float* __restrict__ bnv) {
    __shared__ float sw[4608];
    __shared__ float ssc[64], ssh[64];
    int tid = threadIdx.x;
    for (int i = tid; i < 4608; i += 256) sw[i] = dww[i];
    if (tid < 64) {
        float sc = bng[tid] * rsqrtf(bnv[tid] + 1e-5f);
        ssc[tid] = sc; ssh[tid] = bnb[tid] - bnm[tid] * sc;
    }
    __syncthreads();
    int t = blockIdx.x * 256 + tid;
    int p4 = t << 2;
    int bb = p4 >> 16, pix = p4 & 65535;
    int r = pix >> 8, c0 = pix & 255;
    int rm = r ? r - 1 : 1;
    int rp = (r == 255) ? 254 : r + 1;
    int ro0 = rm << 8, ro1 = r << 8, ro2 = rp << 8;
    int cols[6];
    #pragma unroll
    for (int k = 0; k < 6; k++) {
        int cx = c0 + k - 1;
        cols[k] = cx < 0 ? -cx : (cx > 255 ? 510 - cx : cx);
    }
    const float* mb = g_m + ((size_t)bb << 24);
    size_t obase = ((size_t)bb << 22) + pix;
    for (int cc = 0; cc < 32; cc++) {
        float A[4]={0,0,0,0}, Bx[4]={0,0,0,0}, Cx[4]={0,0,0,0}, Dx[4]={0,0,0,0};
        const float* w1a = sw + (2*cc)    * 36;
        const float* w1b = sw + (2*cc+1)  * 36;
        const float* w2a = sw + (64+2*cc) * 36;
        const float* w2b = sw + (65+2*cc) * 36;
        #pragma unroll
        for (int i = 0; i < 4; i++) {
            const float* p1 = mb + ((size_t)(4*cc + i)       << 16);
            const float* p2 = mb + ((size_t)(128 + 4*cc + i) << 16);
            float v1[18], v2[18];
            #pragma unroll
            for (int k = 0; k < 6; k++) {
                v1[k]    = p1[ro0 + cols[k]]; v1[6+k]  = p1[ro1 + cols[k]]; v1[12+k] = p1[ro2 + cols[k]];
                v2[k]    = p2[ro0 + cols[k]]; v2[6+k]  = p2[ro1 + cols[k]]; v2[12+k] = p2[ro2 + cols[k]];
            }
            #pragma unroll
            for (int ky = 0; ky < 3; ky++)
                #pragma unroll
                for (int kx = 0; kx < 3; kx++) {
                    float wa = w1a[i*9+ky*3+kx], wb = w1b[i*9+ky*3+kx];
                    float wc = w2a[i*9+ky*3+kx], wd = w2b[i*9+ky*3+kx];
                    #pragma unroll
                    for (int j = 0; j < 4; j++) {
                        float u1 = v1[ky*6 + j + kx], u2 = v2[ky*6 + j + kx];
                        A[j]  += wa * u1; Bx[j] += wb * u1;
                        Cx[j] += wc * u2; Dx[j] += wd * u2;
                    }
                }
        }
        int c1 = 2*cc, c2 = 2*cc + 1;
        float r1[4], r2[4];
        #pragma unroll
        for (int j = 0; j < 4; j++) {
            float s1 = A[j]  / (1.f + expf(-A[j]))  * Cx[j];
            float s2 = Bx[j] / (1.f + expf(-Bx[j])) * Dx[j];
            r1[j] = s1 * ssc[c1] + ssh[c1];
            r2[j] = s2 * ssc[c2] + ssh[c2];
        }
        *(float4*)(&g_gt[obase + ((size_t)c1 << 16)]) = make_float4(r1[0], r1[1], r1[2], r1[3]);
        *(float4*)(&g_gt[obase + ((size_t)c2 << 16)]) = make_float4(r2[0], r2[1], r2[2], r2[3]);
    }
}

// ---------------- K7b: out_w 1x1 + final residual, f32x2 ------------------------
__global__ void __launch_bounds__(256) k_out(const float* __restrict__ ow,
                                             float* __restrict__ out) {
    __shared__ __align__(16) float s[4096];
    int tid = threadIdx.x;
    for (int i = tid; i < 4096; i += 256) s[i] = ow[i];
    __syncthreads();
    int p = blockIdx.x * 256 + tid; int bb = p >> 16, pix = p & 65535;
    size_t base = ((size_t)bb << 22) + pix;
    unsigned long long inp[32];
    #pragma unroll
    for (int c = 0; c < 32; c++) {
        float a = g_gt[base + ((size_t)(2*c)   << 16)];
        float b = g_gt[base + ((size_t)(2*c+1) << 16)];
        inp[c] = pk2(a, b);
    }
    #pragma unroll 4
    for (int oc = 0; oc < 64; oc++) {
        const ulonglong2* row = (const ulonglong2*)(s + (oc << 6));
        unsigned long long acc = 0ull;
        #pragma unroll
        for (int c4 = 0; c4 < 16; c4++) {
            ulonglong2 w2 = row[c4];
            fma2(acc, w2.x, inp[2*c4]); fma2(acc, w2.y, inp[2*c4+1]);
        }
        size_t oi = base + ((size_t)oc << 16);
        out[oi] = g_xn[oi] + hadd2(acc);
    }
}

// ---------------- launch ---------------------------------------------------------
extern "C" void kernel_launch(void* const* d_in, const int* in_sizes, int n_in,
                              void* d_out, int out_size) {
    const float* x     = (const float*)d_in[0];
    const float* ln1w  = (const float*)d_in[1];
    const float* ln1b  = (const float*)d_in[2];
    const float* ln2w  = (const float*)d_in[3];
    const float* ln2b  = (const float*)d_in[4];
    const float* dww   = (const float*)d_in[5];
    const float* qw    = (const float*)d_in[6];
    const float* kw    = (const float*)d_in[7];
    const float* vw    = (const float*)d_in[8];
    const float* projw = (const float*)d_in[9];
    const float* mlpw  = (const float*)d_in[10];
    const float* mdww  = (const float*)d_in[11];
    const float* bng   = (const float*)d_in[12];
    const float* bnb   = (const float*)d_in[13];
    const float* bnm   = (const float*)d_in[14];
    const float* bnv   = (const float*)d_in[15];
    const float* ow    = (const float*)d_in[16];
    float* out = (float*)d_out;

    cudaFuncSetAttribute(k_fuse, cudaFuncAttributeMaxDynamicSharedMemorySize, 20608 * 4);

    k_zero<<<8, 256>>>();
    k_ln1<<<1024, 256>>>(x, ln1w, ln1b);
    k_dw<<<65536, 256>>>(dww);
    k_qkv<<<1024, 256>>>(qw, kw, vw);
    dim3 gs(8, 8, 4);
    k_stats<<<gs, 256>>>();
    k_attw<<<1, 256>>>();
    k_mix<<<4, 64>>>(projw);
    dim3 gf(256, 4);
    k_fuse<<<gf, 256, 20608 * 4>>>(x, ln2w, ln2b, mlpw);
    k_mlpdw<<<256, 256>>>(mdww, bng, bnb, bnm, bnv);
    k_out<<<1024, 256>>>(ow, out);
}